// round 11
// baseline (speedup 1.0000x reference)
#include <cuda_runtime.h>
#include <math.h>

typedef unsigned long long ull;

#define BB 8
#define NN 64
#define HH 128
#define HEADS 4
#define HD 128
#define INNER 512
#define EE 8
#define NEdg 4032
#define LL 8
#define ROWS (BB*NN)   // 512
#define JB 8
#define NB 512
#define NT 256
#define NPROJ 416      // 26 ct x 16 rt (32-row tiles)
#define NRT 16

// ---------- persistent scratch ----------
__device__ float g_bufA[ROWS*HH];
__device__ float g_bufB[ROWS*HH];
__device__ float g_q[ROWS*INNER];
__device__ float g_k[ROWS*INNER];
__device__ float g_v[ROWS*INNER];
__device__ float g_P[ROWS*EE];
__device__ float g_D[ROWS*EE];
__device__ int   g_eid[NN*NN];
__device__ unsigned g_bar_cnt;
__device__ unsigned g_bar_gen;
// dataflow flags
__device__ unsigned g_tflag[NRT*26];   // proj tile (rt, ct) -> layer stamp l+1
__device__ unsigned g_row_done[NRT];   // attn CTAs done per 32-row half-graph (cumulative)
__device__ unsigned g_node_done;

// ---------- packed f32x2 helpers ----------
__device__ __forceinline__ ull fma2(ull a, ull b, ull c) {
    ull d; asm("fma.rn.f32x2 %0, %1, %2, %3;" : "=l"(d) : "l"(a), "l"(b), "l"(c)); return d;
}
__device__ __forceinline__ ull pk2(float x, float y) {
    ull r; unsigned a = __float_as_uint(x), b = __float_as_uint(y);
    asm("mov.b64 %0, {%1, %2};" : "=l"(r) : "r"(a), "r"(b)); return r;
}
__device__ __forceinline__ float f2sum(ull v) {
    unsigned a, b;
    asm("mov.b64 {%0, %1}, %2;" : "=r"(a), "=r"(b) : "l"(v));
    return __uint_as_float(a) + __uint_as_float(b);
}

// ---------- single init-time grid barrier ----------
__device__ __forceinline__ void grid_sync() {
    __syncthreads();
    if (threadIdx.x == 0) {
        __threadfence();
        unsigned gen = *(volatile unsigned*)&g_bar_gen;
        if (atomicAdd(&g_bar_cnt, 1u) == NB - 1) {
            *(volatile unsigned*)&g_bar_cnt = 0u;
            __threadfence();
            *(volatile unsigned*)&g_bar_gen = gen + 1u;
        } else {
            while (*(volatile unsigned*)&g_bar_gen == gen) { }
        }
        __threadfence();
    }
    __syncthreads();
}

__global__ void __launch_bounds__(NT, 4) mega(
    const float* __restrict__ noise, const float* __restrict__ edge_attr,
    const int* __restrict__ eidx,
    const float* __restrict__ fc1_w, const float* __restrict__ fc1_b,
    const float* __restrict__ qw, const float* __restrict__ qb,
    const float* __restrict__ kw, const float* __restrict__ kb,
    const float* __restrict__ vw, const float* __restrict__ vb,
    const float* __restrict__ ew,
    const float* __restrict__ sw, const float* __restrict__ sb,
    const float* __restrict__ atom_w, const float* __restrict__ atom_b,
    const float* __restrict__ other_w, const float* __restrict__ other_b,
    const float* __restrict__ efw, const float* __restrict__ efb,
    float* __restrict__ out)
{
    __shared__ __align__(16) float smem[10912];   // 43.6KB; 4 CTAs/SM = 174KB
    const int t = threadIdx.x, blk = blockIdx.x;
    const int w = t >> 5, lane = t & 31;

    // ================= init + flag reset =================
    if (blk < BB && t < HH) {
        float acc = fc1_b[t];
        #pragma unroll 4
        for (int i = 0; i < 128; i++) acc += noise[blk*128 + i] * fc1_w[i*HH + t];
        acc = fmaxf(acc, 0.f);
        for (int n = 0; n < NN; n++) g_bufA[(blk*NN + n)*HH + t] = acc;
    }
    { int e = blk*NT + t; if (e < NEdg) g_eid[eidx[e]*NN + eidx[NEdg + e]] = e; }
    if (blk == 8) { if (t < 256) g_tflag[t] = 0u; }
    if (blk == 9) {
        if (t < 160) g_tflag[256 + t] = 0u;
        else if (t < 160 + NRT) g_row_done[t - 160] = 0u;
        else if (t == 160 + NRT) g_node_done = 0u;
    }
    grid_sync();

    float* xin = g_bufA;
    float* xout = g_bufB;

    for (int l = 0; l < LL; l++) {
        // ============ proj: 32x64 tiles (416 jobs); gated per row-half ============
        if (blk < NPROJ) {
            int ct = blk % 26, rt = blk / 26;
            if (t == 0 && l) {
                while (*(volatile unsigned*)&g_row_done[rt] < (unsigned)(16*l)) { }
            }
            __syncthreads();
            if (t == 0) __threadfence();   // CCTL.IVALL: SM L1 coherent
            __syncthreads();

            ull* AsU = (ull*)smem;             // 2 x [8 kp][33]
            ull* BsU = ((ull*)smem) + 528;     // 2 x [8 kp][64]
            const float* W; const float* bias; int ld, coff; float* outp;
            if (ct < 8)       { W = qw + l*HH*INNER; bias = qb + l*INNER; ld = INNER; coff = ct*64;      outp = g_q; }
            else if (ct < 16) { W = kw + l*HH*INNER; bias = kb + l*INNER; ld = INNER; coff = (ct-8)*64;  outp = g_k; }
            else if (ct < 24) { W = vw + l*HH*INNER; bias = vb + l*INNER; ld = INNER; coff = (ct-16)*64; outp = g_v; }
            else              { W = sw + l*HH*HH;    bias = sb + l*HH;    ld = HH;    coff = (ct-24)*64; outp = xout; }
            const int tx = t & 15, ty = t >> 4;
            const int r0 = rt * 32;
            const int arow = t >> 3, akp = t & 7;
            const int bkp = t >> 5, bcol2 = (t & 31) << 1;
            const float* ap  = &xin[(r0 + arow)*HH + akp*2];
            const float* bp0 = &W[(2*bkp)*ld + coff + bcol2];
            const float* bp1 = &W[(2*bkp + 1)*ld + coff + bcol2];
            ull acc[2][4];
            #pragma unroll
            for (int r = 0; r < 2; r++)
                #pragma unroll
                for (int c = 0; c < 4; c++) acc[r][c] = 0ull;
            float2 av  = *(const float2*)ap;
            float2 b0v = *(const float2*)bp0;
            float2 b1v = *(const float2*)bp1;
            #pragma unroll
            for (int k0i = 0; k0i < 8; k0i++) {
                int asel = (k0i & 1) * 264;
                int bsel = (k0i & 1) * 512;
                AsU[asel + akp*33 + arow] = pk2(fmaxf(av.x, 0.f), fmaxf(av.y, 0.f));
                ulonglong2 bb;
                bb.x = pk2(b0v.x, b1v.x);
                bb.y = pk2(b0v.y, b1v.y);
                *(ulonglong2*)&BsU[bsel + bkp*64 + bcol2] = bb;
                __syncthreads();
                if (k0i < 7) {
                    int k0 = (k0i + 1) * 16;
                    av  = *(const float2*)(ap + k0);
                    b0v = *(const float2*)(bp0 + (size_t)k0*ld);
                    b1v = *(const float2*)(bp1 + (size_t)k0*ld);
                }
                const ull* Ab = AsU + asel;
                const ull* Bb = BsU + bsel;
                #pragma unroll
                for (int kp = 0; kp < 8; kp++) {
                    ull a0 = Ab[kp*33 + ty];
                    ull a1 = Ab[kp*33 + ty + 16];
                    #pragma unroll
                    for (int c = 0; c < 4; c++) {
                        ull bv = Bb[kp*64 + tx + 16*c];
                        acc[0][c] = fma2(a0, bv, acc[0][c]);
                        acc[1][c] = fma2(a1, bv, acc[1][c]);
                    }
                }
            }
            #pragma unroll
            for (int r = 0; r < 2; r++)
                #pragma unroll
                for (int c = 0; c < 4; c++) {
                    int row = r0 + ty + 16*r, col = coff + tx + 16*c;
                    outp[row*ld + col] = f2sum(acc[r][c]) + bias[col];
                }
            __threadfence();
            __syncthreads();
            if (t == 0) atomicExch(&g_tflag[rt*26 + ct], (unsigned)(l + 1));
        }

        // ============ attn (256 jobs): K smem, V streamed from global ============
        if (blk < 256) {
            int jseg = blk & 7;
            int h = (blk >> 3) & 3;
            int b = blk >> 5;
            int jbase = jseg * JB;
            const float scale = 0.08838834764831845f;  // 1/sqrt(128)

            if (t < 16) {
                int sel = t >> 1;
                int ctf;
                if (sel < 3) ctf = sel*8 + 2*h + 0;
                else if (sel < 6) { /* unreachable split below */ ctf = 0; }
                // ct list: {2h, 2h+1, 8+2h, 9+2h, 16+2h, 17+2h, 24, 25}
                int base = (t >> 2);            // 0..3 -> q,k,v,skip group
                int sub = (t >> 1) & 1;         // which of the pair
                ctf = (base < 3) ? (base*8 + 2*h + sub) : (24 + sub);
                int rtw = 2*b + (t & 1);
                unsigned tgt = (unsigned)(l + 1);
                while (*(volatile unsigned*)&g_tflag[rtw*26 + ctf] < tgt) { }
            }
            __syncthreads();
            if (t == 0) __threadfence();
            __syncthreads();

            float* sKV = smem;            // [64][128] K pair-swizzled
            float* sQ  = smem + 8192;     // [8][128]
            float* sEw = smem + 9216;     // [8][128]
            float (*sS)[68] = (float(*)[68])(smem + 10240);
            float* sQE = smem + 10784;
            float* sAE = smem + 10848;

            {   // eW
                int idx = t * 4;
                *(float4*)&sEw[idx] = *(const float4*)&ew[((size_t)l*EE + (idx >> 7))*INNER + h*HD + (idx & 127)];
            }
            {   // Q
                int idx = t * 4;
                *(float4*)&sQ[idx] = *(const float4*)&g_q[(b*NN + jbase + (idx >> 7))*INNER + h*HD + (idx & 127)];
            }
            // K pair-swizzled: pair p of row r at sKV[r*128 + ((p ^ (r&31))<<1)]
            for (int q4 = t; q4 < NN*32; q4 += NT) {
                int row = q4 >> 5, dq = (q4 & 31) << 2;
                float4 v = *(const float4*)&g_k[(b*NN + row)*INNER + h*HD + dq];
                int rx = row & 31;
                float* base = &sKV[row*128];
                float2 lo = {v.x, v.y}, hi = {v.z, v.w};
                *(float2*)&base[((dq >> 1) ^ rx) << 1] = lo;
                *(float2*)&base[(((dq >> 1) + 1) ^ rx) << 1] = hi;
            }
            __syncthreads();

            // qe[w][f] = q[row w]·eW[f]
            {
                const float* qrow = &sQ[w*HD];
                int f = lane & 7, seg = lane >> 3;
                const float* ewrow = &sEw[f*HD + seg*32];
                const float* qseg  = qrow + seg*32;
                float p = 0.f;
                #pragma unroll
                for (int i = 0; i < 32; i++) {
                    int d = (i + lane) & 31;
                    p += qseg[d] * ewrow[d];
                }
                p += __shfl_xor_sync(0xffffffffu, p, 8);
                p += __shfl_xor_sync(0xffffffffu, p, 16);
                if (lane < 8) sQE[w*8 + lane] = p;
            }
            __syncthreads();

            // scores: warp (jp, ih); lane -> src i = ih*32+lane; rows 2jp, 2jp+1
            {
                int jp = w >> 1, ih = w & 1;
                int i = ih*32 + lane;
                int jl0 = jp*2, jl1 = jp*2 + 1;
                int j0 = jbase + jl0, j1 = jbase + jl1;
                const ull* q0p = (const ull*)&sQ[jl0*HD];
                const ull* q1p = (const ull*)&sQ[jl1*HD];
                const float* kr = &sKV[i*128];
                ull A0 = 0ull, A1 = 0ull;
                #pragma unroll 8
                for (int d2 = 0; d2 < 64; d2++) {
                    ull kv = *(const ull*)&kr[(d2 ^ lane) << 1];
                    A0 = fma2(q0p[d2], kv, A0);
                    A1 = fma2(q1p[d2], kv, A1);
                }
                float dot0 = f2sum(A0), dot1 = f2sum(A1);
                const float* eabase = edge_attr + (size_t)b * NEdg * EE;
                int e0 = (i == j0) ? 0 : g_eid[i*NN + j0];
                int e1 = (i == j1) ? 0 : g_eid[i*NN + j1];
                float4 p0a = *(const float4*)&eabase[e0*EE];
                float4 p0b = *(const float4*)&eabase[e0*EE + 4];
                float4 p1a = *(const float4*)&eabase[e1*EE];
                float4 p1b = *(const float4*)&eabase[e1*EE + 4];
                const float* qe0 = &sQE[jl0*8];
                const float* qe1 = &sQE[jl1*8];
                float bs0 = p0a.x*qe0[0] + p0a.y*qe0[1] + p0a.z*qe0[2] + p0a.w*qe0[3]
                          + p0b.x*qe0[4] + p0b.y*qe0[5] + p0b.z*qe0[6] + p0b.w*qe0[7];
                float bs1 = p1a.x*qe1[0] + p1a.y*qe1[1] + p1a.z*qe1[2] + p1a.w*qe1[3]
                          + p1b.x*qe1[4] + p1b.y*qe1[5] + p1b.z*qe1[6] + p1b.w*qe1[7];
                sS[jl0][i] = (i == j0) ? -1e30f : (dot0 + bs0) * scale;
                sS[jl1][i] = (i == j1) ? -1e30f : (dot1 + bs1) * scale;
            }
            __syncthreads();

            // softmax + aggE: warp w owns row w
            {
                int jg = jbase + w;
                float s1 = sS[w][lane], s2 = sS[w][lane + 32];
                float m = fmaxf(s1, s2);
                #pragma unroll
                for (int o = 1; o < 32; o <<= 1) m = fmaxf(m, __shfl_xor_sync(0xffffffffu, m, o));
                float x1 = __expf(s1 - m), x2 = __expf(s2 - m);
                float sum = x1 + x2;
                #pragma unroll
                for (int o = 1; o < 32; o <<= 1) sum += __shfl_xor_sync(0xffffffffu, sum, o);
                float inv = 1.f / sum;
                float al1 = x1 * inv, al2 = x2 * inv;
                sS[w][lane] = al1;
                sS[w][lane + 32] = al2;
                int i1 = lane, i2 = lane + 32;
                const float* eabase = edge_attr + (size_t)b * NEdg * EE;
                int e1 = (i1 == jg) ? 0 : g_eid[i1*NN + jg];
                int e2 = (i2 == jg) ? 0 : g_eid[i2*NN + jg];
                float4 ea1a = *(const float4*)&eabase[e1*EE];
                float4 ea1b = *(const float4*)&eabase[e1*EE + 4];
                float4 ea2a = *(const float4*)&eabase[e2*EE];
                float4 ea2b = *(const float4*)&eabase[e2*EE + 4];
                float ea1[8] = {ea1a.x, ea1a.y, ea1a.z, ea1a.w, ea1b.x, ea1b.y, ea1b.z, ea1b.w};
                float ea2[8] = {ea2a.x, ea2a.y, ea2a.z, ea2a.w, ea2b.x, ea2b.y, ea2b.z, ea2b.w};
                float ae[8];
                #pragma unroll
                for (int f = 0; f < 8; f++) {
                    float v = al1*ea1[f] + al2*ea2[f];
                    #pragma unroll
                    for (int o = 1; o < 32; o <<= 1) v += __shfl_xor_sync(0xffffffffu, v, o);
                    ae[f] = v;
                }
                if (lane == 0) {
                    #pragma unroll
                    for (int f = 0; f < 8; f++) sAE[w*8 + f] = ae[f];
                }
            }
            __syncthreads();

            // aggV: warp (jp2, dh); rows 2jp2, 2jp2+1; lane d = dh*64 + lane*2; V from GLOBAL
            {
                int jp2 = w >> 1, dh = w & 1;
                int jl0 = jp2*2, jl1 = jl0 + 1;
                int d0 = dh*64 + lane*2;
                const float* vp = &g_v[(size_t)(b*NN)*INNER + h*HD + d0];
                float a00 = 0.f, a01 = 0.f, a10 = 0.f, a11 = 0.f;
                #pragma unroll 4
                for (int i = 0; i < NN; i++) {
                    float2 v = *(const float2*)&vp[(size_t)i*INNER];   // coalesced LDG.64
                    float al0 = sS[jl0][i], al1 = sS[jl1][i];
                    a00 += al0*v.x; a01 += al0*v.y;
                    a10 += al1*v.x; a11 += al1*v.y;
                }
                #pragma unroll
                for (int f = 0; f < 8; f++) {
                    float ae0 = sAE[jl0*8 + f], ae1 = sAE[jl1*8 + f];
                    float2 wv = *(const float2*)&sEw[f*HD + d0];
                    a00 += ae0*wv.x; a01 += ae0*wv.y;
                    a10 += ae1*wv.x; a11 += ae1*wv.y;
                }
                float* d0p = &xout[(b*NN + jbase + jl0)*HH + d0];
                float* d1p = &xout[(b*NN + jbase + jl1)*HH + d0];
                atomicAdd(d0p+0, 0.25f*a00);
                atomicAdd(d0p+1, 0.25f*a01);
                atomicAdd(d1p+0, 0.25f*a10);
                atomicAdd(d1p+1, 0.25f*a11);
            }
            __threadfence();
            __syncthreads();
            if (t == 0) atomicAdd(&g_row_done[b*2 + (jseg >> 2)], 1u);
        }
        float* tmp = xin; xin = xout; xout = tmp;
    }

    // ================= node head + P/D (1 node per block) =================
    {
        if (t == 0) {
            int half = (blk >> 6)*2 + ((blk & 63) >> 5);
            while (*(volatile unsigned*)&g_row_done[half] < (unsigned)(16*LL)) { }
        }
        __syncthreads();
        if (t == 0) __threadfence();
        __syncthreads();

        float* xr   = smem;         // [128]
        float* outs = smem + 128;   // [40]
        float* red  = smem + 168;   // [2]
        int node = blk;
        if (t < 128) xr[t] = fmaxf(xin[node*128 + t], 0.f);
        __syncthreads();
        if (t < 40) {
            float acc;
            if (t < 9)       { acc = atom_b[t];  for (int d = 0; d < HH; d++) acc += xr[d]*atom_w[d*9+t]; }
            else if (t < 24) { int c = t-9;  acc = other_b[c]; for (int d = 0; d < HH; d++) acc += xr[d]*other_w[d*15+c]; }
            else if (t < 32) { int f = t-24; acc = 0.f; for (int d = 0; d < HH; d++) acc += xr[d]*efw[d*EE+f]; }
            else             { int f = t-32; acc = 0.f; for (int d = 0; d < HH; d++) acc += xr[d]*efw[(128+d)*EE+f]; }
            outs[t] = acc;
        }
        __syncthreads();
        if (t == 0) {
            float m = -1e30f;
            for (int a = 0; a < 9; a++) m = fmaxf(m, outs[a]);
            float s = 0.f;
            for (int a = 0; a < 9; a++) s += __expf(outs[a]-m);
            red[0] = m; red[1] = s;
        }
        __syncthreads();
        if (t < 9) {
            float p = __expf(outs[t]-red[0]) / red[1];
            out[node*24 + t] = 1.f/(1.f + __expf(-p));
        } else if (t < 24) {
            float o = 1.f/(1.f + __expf(-outs[t]));
            out[node*24 + t] = 1.f/(1.f + __expf(-o));
        } else if (t < 32) {
            g_P[node*EE + (t-24)] = outs[t];
        } else if (t < 40) {
            g_D[node*EE + (t-32)] = outs[t];
        }
        __threadfence();
        __syncthreads();
        if (t == 0) atomicAdd(&g_node_done, 1u);
    }

    // ================= edge head =================
    {
        if (t == 0) {
            while (*(volatile unsigned*)&g_node_done < (unsigned)NB) { }
        }
        __syncthreads();
        if (t == 0) __threadfence();
        __syncthreads();
        if (t < 63) {
            int eg = blk*63 + t;     // 512*63 = 32256 exactly
            int b = eg / NEdg, e = eg % NEdg;
            int s = eidx[e], d = eidx[NEdg + e];
            const float* P = &g_P[(b*NN + s)*EE];
            const float* D = &g_D[(b*NN + d)*EE];
            float* o = out + (size_t)ROWS*24 + (size_t)eg*EE;
            #pragma unroll
            for (int f = 0; f < EE; f++) {
                float v = P[f] + D[f] + efb[f];
                o[f] = 1.f/(1.f + __expf(-v));
            }
        }
    }
}

extern "C" void kernel_launch(void* const* d_in, const int* in_sizes, int n_in,
                              void* d_out, int out_size) {
    const float* noise     = (const float*)d_in[0];
    const float* edge_attr = (const float*)d_in[1];
    const int*   edge_index= (const int*)  d_in[2];
    const float* fc1_w     = (const float*)d_in[3];
    const float* fc1_b     = (const float*)d_in[4];
    const float* q_w       = (const float*)d_in[5];
    const float* q_b       = (const float*)d_in[6];
    const float* k_w       = (const float*)d_in[7];
    const float* k_b       = (const float*)d_in[8];
    const float* v_w       = (const float*)d_in[9];
    const float* v_b       = (const float*)d_in[10];
    const float* e_w       = (const float*)d_in[11];
    const float* skip_w    = (const float*)d_in[12];
    const float* skip_b    = (const float*)d_in[13];
    const float* atom_w    = (const float*)d_in[14];
    const float* atom_b    = (const float*)d_in[15];
    const float* other_w   = (const float*)d_in[16];
    const float* other_b   = (const float*)d_in[17];
    const float* efw       = (const float*)d_in[18];
    const float* efb       = (const float*)d_in[19];
    float* out = (float*)d_out;

    cudaFuncSetAttribute(mega, cudaFuncAttributePreferredSharedMemoryCarveout, 100);
    mega<<<NB, NT>>>(noise, edge_attr, edge_index, fc1_w, fc1_b,
                     q_w, q_b, k_w, k_b, v_w, v_b, e_w, skip_w, skip_b,
                     atom_w, atom_b, other_w, other_b, efw, efb, out);
}

// round 12
// speedup vs baseline: 1.1568x; 1.1568x over previous
#include <cuda_runtime.h>
#include <math.h>

typedef unsigned long long ull;

#define BB 8
#define NN 64
#define HH 128
#define HEADS 4
#define HD 128
#define INNER 512
#define EE 8
#define NEdg 4032
#define LL 8
#define ROWS (BB*NN)   // 512
#define SPLITJ 8
#define JB (NN/SPLITJ) // 8
#define NB 256
#define NT 256

// ---------- persistent scratch ----------
__device__ float g_bufA[ROWS*HH];
__device__ float g_bufB[ROWS*HH];
__device__ float g_q[ROWS*INNER];
__device__ float g_k[ROWS*INNER];
__device__ float g_v[ROWS*INNER];
__device__ float g_P[ROWS*EE];
__device__ float g_D[ROWS*EE];
__device__ int   g_eid[NN*NN];
__device__ unsigned g_bar_cnt;
__device__ unsigned g_bar_gen;

// ---------- packed f32x2 helpers ----------
__device__ __forceinline__ ull fma2(ull a, ull b, ull c) {
    ull d; asm("fma.rn.f32x2 %0, %1, %2, %3;" : "=l"(d) : "l"(a), "l"(b), "l"(c)); return d;
}
__device__ __forceinline__ ull pk2(float x, float y) {
    ull r; unsigned a = __float_as_uint(x), b = __float_as_uint(y);
    asm("mov.b64 %0, {%1, %2};" : "=l"(r) : "r"(a), "r"(b)); return r;
}
__device__ __forceinline__ float f2sum(ull v) {
    unsigned a, b;
    asm("mov.b64 {%0, %1}, %2;" : "=r"(a), "=r"(b) : "l"(v));
    return __uint_as_float(a) + __uint_as_float(b);
}

// ---------- grid barriers ----------
// Writer-release: each CTA's thread0 fences (membar.gl) before arriving, so all
// the CTA's prior STG/atomics are L2-visible before the generation flips.
// Reader side does NOT fence: consumers read dynamic data with ld.cg (L2 is the
// coherence point), so no CCTL.IVALL is needed and read-only data stays L1-hot.
__device__ __forceinline__ void grid_sync_fast() {
    __syncthreads();
    if (threadIdx.x == 0) {
        __threadfence();   // release
        unsigned gen = *(volatile unsigned*)&g_bar_gen;
        if (atomicAdd(&g_bar_cnt, 1u) == NB - 1) {
            *(volatile unsigned*)&g_bar_cnt = 0u;
            __threadfence();
            *(volatile unsigned*)&g_bar_gen = gen + 1u;
        } else {
            while (*(volatile unsigned*)&g_bar_gen == gen) { __nanosleep(32); }
        }
    }
    __syncthreads();
}
// init barrier: full acquire (CCTL.IVALL) — used once, so the L1-resident
// eid/edge_attr working set survives the rest of the kernel.
__device__ __forceinline__ void grid_sync_init() {
    __syncthreads();
    if (threadIdx.x == 0) {
        __threadfence();
        unsigned gen = *(volatile unsigned*)&g_bar_gen;
        if (atomicAdd(&g_bar_cnt, 1u) == NB - 1) {
            *(volatile unsigned*)&g_bar_cnt = 0u;
            __threadfence();
            *(volatile unsigned*)&g_bar_gen = gen + 1u;
        } else {
            while (*(volatile unsigned*)&g_bar_gen == gen) { __nanosleep(32); }
        }
        __threadfence();   // acquire (once)
    }
    __syncthreads();
}

__global__ void __launch_bounds__(NT, 2) mega(
    const float* __restrict__ noise, const float* __restrict__ edge_attr,
    const int* __restrict__ eidx,
    const float* __restrict__ fc1_w, const float* __restrict__ fc1_b,
    const float* __restrict__ qw, const float* __restrict__ qb,
    const float* __restrict__ kw, const float* __restrict__ kb,
    const float* __restrict__ vw, const float* __restrict__ vb,
    const float* __restrict__ ew,
    const float* __restrict__ sw, const float* __restrict__ sb,
    const float* __restrict__ atom_w, const float* __restrict__ atom_b,
    const float* __restrict__ other_w, const float* __restrict__ other_b,
    const float* __restrict__ efw, const float* __restrict__ efb,
    float* __restrict__ out)
{
    __shared__ __align__(16) float smem[10912];   // 43.6KB; 2 CTAs/SM
    const int t = threadIdx.x, blk = blockIdx.x;
    const int w = t >> 5, lane = t & 31;

    // ================= init =================
    if (blk < BB && t < HH) {
        float acc = fc1_b[t];
        #pragma unroll 4
        for (int i = 0; i < 128; i++) acc += noise[blk*128 + i] * fc1_w[i*HH + t];
        acc = fmaxf(acc, 0.f);
        for (int n = 0; n < NN; n++) g_bufA[(blk*NN + n)*HH + t] = acc;
    }
    { int e = blk*NT + t; if (e < NEdg) g_eid[eidx[e]*NN + eidx[NEdg + e]] = e; }
    grid_sync_init();

    float* xin = g_bufA;
    float* xout = g_bufB;

    for (int l = 0; l < LL; l++) {
        // ============ proj: 64x64 tiles; double-buffered; pair-interleaved ull smem ============
        if (blk < 208) {
            ull* AsU = (ull*)smem;           // [2][8 kp][64 rows]
            ull* BsU = ((ull*)smem) + 1024;  // [2][8 kp][64 cols]
            int ct = blk % 26, rt = blk / 26;
            const float* W; const float* bias; int ld, coff; float* outp;
            if (ct < 8)       { W = qw + l*HH*INNER; bias = qb + l*INNER; ld = INNER; coff = ct*64;      outp = g_q; }
            else if (ct < 16) { W = kw + l*HH*INNER; bias = kb + l*INNER; ld = INNER; coff = (ct-8)*64;  outp = g_k; }
            else if (ct < 24) { W = vw + l*HH*INNER; bias = vb + l*INNER; ld = INNER; coff = (ct-16)*64; outp = g_v; }
            else              { W = sw + l*HH*HH;    bias = sb + l*HH;    ld = HH;    coff = (ct-24)*64; outp = xout; }
            const int tx = t & 15, ty = t >> 4;
            const int row_a = t & 63, kq = t >> 6;
            const int col_b = t & 63, kpb = t >> 6;
            int r0 = rt*64;
            ull acc[4][4];
            #pragma unroll
            for (int r = 0; r < 4; r++)
                #pragma unroll
                for (int c = 0; c < 4; c++) acc[r][c] = 0ull;
            const float* arow_p = &xin[(r0+row_a)*HH + kq*4];
            const float* bcol_p = &W[coff + col_b];
            // prefetch k-tile 0 (xin via ld.cg: produced by other CTAs, L2-coherent)
            float4 a4 = __ldcg((const float4*)arow_p);
            float bw0 = bcol_p[(2*kpb)*ld],     bw1 = bcol_p[(2*kpb+1)*ld];
            float bw2 = bcol_p[(2*kpb+8)*ld],   bw3 = bcol_p[(2*kpb+9)*ld];
            #pragma unroll
            for (int k0i = 0; k0i < 8; k0i++) {
                int bsel = (k0i & 1) << 9;
                AsU[bsel + (2*kq)*64 + row_a]   = pk2(fmaxf(a4.x,0.f), fmaxf(a4.y,0.f));
                AsU[bsel + (2*kq+1)*64 + row_a] = pk2(fmaxf(a4.z,0.f), fmaxf(a4.w,0.f));
                BsU[bsel + kpb*64 + col_b]      = pk2(bw0, bw1);
                BsU[bsel + (kpb+4)*64 + col_b]  = pk2(bw2, bw3);
                __syncthreads();
                if (k0i < 7) {
                    int k0 = (k0i+1)*16;
                    a4 = __ldcg((const float4*)(arow_p + k0));
                    bw0 = bcol_p[(k0 + 2*kpb)*ld];   bw1 = bcol_p[(k0 + 2*kpb+1)*ld];
                    bw2 = bcol_p[(k0 + 2*kpb+8)*ld]; bw3 = bcol_p[(k0 + 2*kpb+9)*ld];
                }
                const ull* Ab = AsU + bsel;
                const ull* Bb = BsU + bsel;
                #pragma unroll
                for (int kp = 0; kp < 8; kp++) {
                    ull a2[4], b2[4];
                    #pragma unroll
                    for (int r = 0; r < 4; r++) a2[r] = Ab[kp*64 + ty + 16*r];
                    #pragma unroll
                    for (int c = 0; c < 4; c++) b2[c] = Bb[kp*64 + tx + 16*c];
                    #pragma unroll
                    for (int r = 0; r < 4; r++)
                        #pragma unroll
                        for (int c = 0; c < 4; c++) acc[r][c] = fma2(a2[r], b2[c], acc[r][c]);
                }
            }
            #pragma unroll
            for (int r = 0; r < 4; r++)
                #pragma unroll
                for (int c = 0; c < 4; c++) {
                    int row = r0 + ty + 16*r, col = coff + tx + 16*c;
                    outp[row*ld + col] = f2sum(acc[r][c]) + bias[col];
                }
        }
        grid_sync_fast();

        // ============ attn: 2 dst rows per reader warp; K smem, V smem restage ============
        {
            float* sKV = smem;            // [64][128]: K swizzled, then V linear
            float* sQ  = smem + 8192;     // [8][128]
            float* sEw = smem + 9216;     // [8][128]
            float (*sS)[68] = (float(*)[68])(smem + 10240);
            float* sQE = smem + 10784;
            float* sAE = smem + 10848;
            int jseg = blk & 7;
            int h = (blk >> 3) & 3;
            int b = blk >> 5;
            int jbase = jseg * JB;
            const float scale = 0.08838834764831845f;  // 1/sqrt(128)

            {   // eW (read-only input: normal ld, stays L1-hot across layers)
                int idx = t * 4;
                *(float4*)&sEw[idx] = *(const float4*)&ew[((size_t)l*EE + (idx >> 7))*INNER + h*HD + (idx & 127)];
            }
            {   // Q (dynamic: ld.cg)
                int idx = t * 4;
                *(float4*)&sQ[idx] = __ldcg((const float4*)&g_q[(b*NN + jbase + (idx >> 7))*INNER + h*HD + (idx & 127)]);
            }
            // K pair-swizzled (dynamic: ld.cg)
            for (int q4 = t; q4 < NN*32; q4 += NT) {
                int row = q4 >> 5, dq = (q4 & 31) << 2;
                float4 v = __ldcg((const float4*)&g_k[(b*NN + row)*INNER + h*HD + dq]);
                int rx = row & 31;
                float* base = &sKV[row*128];
                float2 lo = {v.x, v.y}, hi = {v.z, v.w};
                *(float2*)&base[((dq >> 1) ^ rx) << 1] = lo;
                *(float2*)&base[(((dq >> 1) + 1) ^ rx) << 1] = hi;
            }
            __syncthreads();

            // qe[w][f] = q[row w]·eW[f]
            {
                const float* qrow = &sQ[w*HD];
                int f = lane & 7, seg = lane >> 3;
                const float* ewrow = &sEw[f*HD + seg*32];
                const float* qseg  = qrow + seg*32;
                float p = 0.f;
                #pragma unroll
                for (int i = 0; i < 32; i++) {
                    int d = (i + lane) & 31;
                    p += qseg[d] * ewrow[d];
                }
                p += __shfl_xor_sync(0xffffffffu, p, 8);
                p += __shfl_xor_sync(0xffffffffu, p, 16);
                if (lane < 8) sQE[w*8 + lane] = p;
            }
            __syncthreads();

            // scores: warp (jp, ih); lane -> src i = ih*32+lane, rows 2jp, 2jp+1
            {
                int jp = w >> 1, ih = w & 1;
                int i = ih*32 + lane;
                int jl0 = jp*2, jl1 = jp*2 + 1;
                int j0 = jbase + jl0, j1 = jbase + jl1;
                const ull* q0p = (const ull*)&sQ[jl0*HD];
                const ull* q1p = (const ull*)&sQ[jl1*HD];
                const float* kr = &sKV[i*128];
                ull A0 = 0ull, A1 = 0ull;
                #pragma unroll 8
                for (int d2 = 0; d2 < 64; d2++) {
                    ull kv = *(const ull*)&kr[(d2 ^ lane) << 1];
                    A0 = fma2(q0p[d2], kv, A0);
                    A1 = fma2(q1p[d2], kv, A1);
                }
                float dot0 = f2sum(A0), dot1 = f2sum(A1);
                const float* eabase = edge_attr + (size_t)b * NEdg * EE;
                int e0 = (i == j0) ? 0 : g_eid[i*NN + j0];
                int e1 = (i == j1) ? 0 : g_eid[i*NN + j1];
                float4 p0a = *(const float4*)&eabase[e0*EE];
                float4 p0b = *(const float4*)&eabase[e0*EE + 4];
                float4 p1a = *(const float4*)&eabase[e1*EE];
                float4 p1b = *(const float4*)&eabase[e1*EE + 4];
                const float* qe0 = &sQE[jl0*8];
                const float* qe1 = &sQE[jl1*8];
                float bs0 = p0a.x*qe0[0] + p0a.y*qe0[1] + p0a.z*qe0[2] + p0a.w*qe0[3]
                          + p0b.x*qe0[4] + p0b.y*qe0[5] + p0b.z*qe0[6] + p0b.w*qe0[7];
                float bs1 = p1a.x*qe1[0] + p1a.y*qe1[1] + p1a.z*qe1[2] + p1a.w*qe1[3]
                          + p1b.x*qe1[4] + p1b.y*qe1[5] + p1b.z*qe1[6] + p1b.w*qe1[7];
                sS[jl0][i] = (i == j0) ? -1e30f : (dot0 + bs0) * scale;
                sS[jl1][i] = (i == j1) ? -1e30f : (dot1 + bs1) * scale;
            }
            __syncthreads();

            // V restage (ld.cg; issue early, readers wait at next sync)
            for (int idx = t*4; idx < NN*HD; idx += NT*4)
                *(float4*)&sKV[idx] = __ldcg((const float4*)&g_v[(b*NN + (idx >> 7))*INNER + h*HD + (idx & 127)]);

            // softmax + aggE: warp w owns row w
            {
                int jg = jbase + w;
                float s1 = sS[w][lane], s2 = sS[w][lane + 32];
                float m = fmaxf(s1, s2);
                #pragma unroll
                for (int o = 1; o < 32; o <<= 1) m = fmaxf(m, __shfl_xor_sync(0xffffffffu, m, o));
                float x1 = __expf(s1 - m), x2 = __expf(s2 - m);
                float sum = x1 + x2;
                #pragma unroll
                for (int o = 1; o < 32; o <<= 1) sum += __shfl_xor_sync(0xffffffffu, sum, o);
                float inv = 1.f / sum;
                float al1 = x1 * inv, al2 = x2 * inv;
                sS[w][lane] = al1;
                sS[w][lane + 32] = al2;
                int i1 = lane, i2 = lane + 32;
                const float* eabase = edge_attr + (size_t)b * NEdg * EE;
                int e1 = (i1 == jg) ? 0 : g_eid[i1*NN + jg];
                int e2 = (i2 == jg) ? 0 : g_eid[i2*NN + jg];
                float4 ea1a = *(const float4*)&eabase[e1*EE];
                float4 ea1b = *(const float4*)&eabase[e1*EE + 4];
                float4 ea2a = *(const float4*)&eabase[e2*EE];
                float4 ea2b = *(const float4*)&eabase[e2*EE + 4];
                float ea1[8] = {ea1a.x, ea1a.y, ea1a.z, ea1a.w, ea1b.x, ea1b.y, ea1b.z, ea1b.w};
                float ea2[8] = {ea2a.x, ea2a.y, ea2a.z, ea2a.w, ea2b.x, ea2b.y, ea2b.z, ea2b.w};
                float ae[8];
                #pragma unroll
                for (int f = 0; f < 8; f++) {
                    float v = al1*ea1[f] + al2*ea2[f];
                    #pragma unroll
                    for (int o = 1; o < 32; o <<= 1) v += __shfl_xor_sync(0xffffffffu, v, o);
                    ae[f] = v;
                }
                if (lane == 0) {
                    #pragma unroll
                    for (int f = 0; f < 8; f++) sAE[w*8 + f] = ae[f];
                }
            }
            __syncthreads();

            // aggV: warp (jp2, dh); rows 2jp2, 2jp2+1; lane d = dh*64 + lane*2
            {
                int jp2 = w >> 1, dh = w & 1;
                int jl0 = jp2*2, jl1 = jl0 + 1;
                int d0 = dh*64 + lane*2;
                float a00 = 0.f, a01 = 0.f, a10 = 0.f, a11 = 0.f;
                #pragma unroll 4
                for (int i = 0; i < NN; i++) {
                    float al0 = sS[jl0][i], al1 = sS[jl1][i];
                    float2 v = *(const float2*)&sKV[i*HD + d0];
                    a00 += al0*v.x; a01 += al0*v.y;
                    a10 += al1*v.x; a11 += al1*v.y;
                }
                #pragma unroll
                for (int f = 0; f < 8; f++) {
                    float ae0 = sAE[jl0*8 + f], ae1 = sAE[jl1*8 + f];
                    float2 wv = *(const float2*)&sEw[f*HD + d0];
                    a00 += ae0*wv.x; a01 += ae0*wv.y;
                    a10 += ae1*wv.x; a11 += ae1*wv.y;
                }
                float* d0p = &xout[(b*NN + jbase + jl0)*HH + d0];
                float* d1p = &xout[(b*NN + jbase + jl1)*HH + d0];
                atomicAdd(d0p+0, 0.25f*a00);
                atomicAdd(d0p+1, 0.25f*a01);
                atomicAdd(d1p+0, 0.25f*a10);
                atomicAdd(d1p+1, 0.25f*a11);
            }
        }
        grid_sync_fast();
        float* tmp = xin; xin = xout; xout = tmp;
    }

    // ================= node head + P/D (2 nodes per block) =================
    {
        float* xr   = smem;         // [2][128]
        float* outs = smem + 256;   // [2][40]
        float* red  = smem + 336;   // [2][2]
        int sub = t >> 7, tl = t & 127;
        int node = blk*2 + sub;
        xr[sub*128 + tl] = fmaxf(__ldcg(&xin[node*128 + tl]), 0.f);
        __syncthreads();
        if (tl < 40) {
            const float* xp = &xr[sub*128];
            float acc;
            if (tl < 9)       { acc = atom_b[tl];  for (int d = 0; d < HH; d++) acc += xp[d]*atom_w[d*9+tl]; }
            else if (tl < 24) { int c = tl-9;  acc = other_b[c]; for (int d = 0; d < HH; d++) acc += xp[d]*other_w[d*15+c]; }
            else if (tl < 32) { int f = tl-24; acc = 0.f; for (int d = 0; d < HH; d++) acc += xp[d]*efw[d*EE+f]; }
            else              { int f = tl-32; acc = 0.f; for (int d = 0; d < HH; d++) acc += xp[d]*efw[(128+d)*EE+f]; }
            outs[sub*40 + tl] = acc;
        }
        __syncthreads();
        if (tl == 0) {
            float m = -1e30f;
            for (int a = 0; a < 9; a++) m = fmaxf(m, outs[sub*40+a]);
            float s = 0.f;
            for (int a = 0; a < 9; a++) s += __expf(outs[sub*40+a]-m);
            red[sub*2] = m; red[sub*2+1] = s;
        }
        __syncthreads();
        if (tl < 9) {
            float p = __expf(outs[sub*40+tl]-red[sub*2]) / red[sub*2+1];
            out[node*24 + tl] = 1.f/(1.f + __expf(-p));
        } else if (tl < 24) {
            float o = 1.f/(1.f + __expf(-outs[sub*40+tl]));
            out[node*24 + tl] = 1.f/(1.f + __expf(-o));
        } else if (tl < 32) {
            g_P[node*EE + (tl-24)] = outs[sub*40+tl];
        } else if (tl < 40) {
            g_D[node*EE + (tl-32)] = outs[sub*40+tl];
        }
    }
    grid_sync_fast();

    // ================= edge head =================
    if (t < 126) {
        int eg = blk*126 + t;     // 256*126 = 32256
        int b = eg / NEdg, e = eg % NEdg;
        int s = eidx[e], d = eidx[NEdg + e];
        float4 Pa = __ldcg((const float4*)&g_P[(b*NN + s)*EE]);
        float4 Pb = __ldcg((const float4*)&g_P[(b*NN + s)*EE + 4]);
        float4 Da = __ldcg((const float4*)&g_D[(b*NN + d)*EE]);
        float4 Db = __ldcg((const float4*)&g_D[(b*NN + d)*EE + 4]);
        float P[8] = {Pa.x, Pa.y, Pa.z, Pa.w, Pb.x, Pb.y, Pb.z, Pb.w};
        float D[8] = {Da.x, Da.y, Da.z, Da.w, Db.x, Db.y, Db.z, Db.w};
        float* o = out + (size_t)ROWS*24 + (size_t)eg*EE;
        #pragma unroll
        for (int f = 0; f < EE; f++) {
            float v = P[f] + D[f] + efb[f];
            o[f] = 1.f/(1.f + __expf(-v));
        }
    }
}

extern "C" void kernel_launch(void* const* d_in, const int* in_sizes, int n_in,
                              void* d_out, int out_size) {
    const float* noise     = (const float*)d_in[0];
    const float* edge_attr = (const float*)d_in[1];
    const int*   edge_index= (const int*)  d_in[2];
    const float* fc1_w     = (const float*)d_in[3];
    const float* fc1_b     = (const float*)d_in[4];
    const float* q_w       = (const float*)d_in[5];
    const float* q_b       = (const float*)d_in[6];
    const float* k_w       = (const float*)d_in[7];
    const float* k_b       = (const float*)d_in[8];
    const float* v_w       = (const float*)d_in[9];
    const float* v_b       = (const float*)d_in[10];
    const float* e_w       = (const float*)d_in[11];
    const float* skip_w    = (const float*)d_in[12];
    const float* skip_b    = (const float*)d_in[13];
    const float* atom_w    = (const float*)d_in[14];
    const float* atom_b    = (const float*)d_in[15];
    const float* other_w   = (const float*)d_in[16];
    const float* other_b   = (const float*)d_in[17];
    const float* efw       = (const float*)d_in[18];
    const float* efb       = (const float*)d_in[19];
    float* out = (float*)d_out;

    mega<<<NB, NT>>>(noise, edge_attr, edge_index, fc1_w, fc1_b,
                     q_w, q_b, k_w, k_b, v_w, v_b, e_w, skip_w, skip_b,
                     atom_w, atom_b, other_w, other_b, efw, efb, out);
}

// round 15
// speedup vs baseline: 1.4274x; 1.2339x over previous
#include <cuda_runtime.h>
#include <math.h>
#include <cstdint>

typedef unsigned long long ull;

#define BB 8
#define NN 64
#define HH 128
#define HEADS 4
#define HD 128
#define INNER 512
#define EE 8
#define NEdg 4032
#define LL 8
#define ROWS (BB*NN)   // 512
#define SPLITJ 8
#define JB (NN/SPLITJ) // 8
#define NB 256
#define NT 256

// proj smem: A[64][68] uint2 (hi,lo) + B[68-stride] uint2
#define APITCH 68
#define A_U2 (64*APITCH)          // 4352 uint2
#define SMEM_BYTES (2*A_U2*8)     // 69632 B

// ---------- persistent scratch ----------
__device__ float g_bufA[ROWS*HH];
__device__ float g_bufB[ROWS*HH];
__device__ float g_q[ROWS*INNER];
__device__ float g_k[ROWS*INNER];
__device__ float g_v[ROWS*INNER];
__device__ float g_P[ROWS*EE];
__device__ float g_D[ROWS*EE];
__device__ int   g_eid[NN*NN];
__device__ unsigned g_bar_cnt;
__device__ unsigned g_bar_gen;

// ---------- packed f32x2 helpers ----------
__device__ __forceinline__ ull fma2(ull a, ull b, ull c) {
    ull d; asm("fma.rn.f32x2 %0, %1, %2, %3;" : "=l"(d) : "l"(a), "l"(b), "l"(c)); return d;
}
__device__ __forceinline__ ull pk2(float x, float y) {
    ull r; unsigned a = __float_as_uint(x), b = __float_as_uint(y);
    asm("mov.b64 %0, {%1, %2};" : "=l"(r) : "r"(a), "r"(b)); return r;
}
__device__ __forceinline__ float f2sum(ull v) {
    unsigned a, b;
    asm("mov.b64 {%0, %1}, %2;" : "=r"(a), "=r"(b) : "l"(v));
    return __uint_as_float(a) + __uint_as_float(b);
}
// pack two fp32 -> bf16x2, memory order [a -> low16, b -> high16]
__device__ __forceinline__ unsigned pkbf(float a, float b) {
    unsigned r; asm("cvt.rn.bf16x2.f32 %0, %1, %2;" : "=r"(r) : "f"(b), "f"(a)); return r;
}
// split pair (f0,f1) into bf16 hi + bf16 residual lo, packed
__device__ __forceinline__ uint2 bfsplit(float f0, float f1) {
    unsigned h = pkbf(f0, f1);
    float r0 = f0 - __uint_as_float(h << 16);
    float r1 = f1 - __uint_as_float(h & 0xffff0000u);
    return make_uint2(h, pkbf(r0, r1));
}
__device__ __forceinline__ void mma_bf16(float* d, unsigned a0, unsigned a1, unsigned a2, unsigned a3,
                                         unsigned b0, unsigned b1) {
    asm volatile("mma.sync.aligned.m16n8k16.row.col.f32.bf16.bf16.f32 "
                 "{%0,%1,%2,%3}, {%4,%5,%6,%7}, {%8,%9}, {%0,%1,%2,%3};"
                 : "+f"(d[0]), "+f"(d[1]), "+f"(d[2]), "+f"(d[3])
                 : "r"(a0), "r"(a1), "r"(a2), "r"(a3), "r"(b0), "r"(b1));
}

// ---------- grid barriers (R12 semantics: release-only fast path; ld.cg coherence) ----------
__device__ __forceinline__ void grid_sync_fast() {
    __syncthreads();
    if (threadIdx.x == 0) {
        __threadfence();   // release
        unsigned gen = *(volatile unsigned*)&g_bar_gen;
        if (atomicAdd(&g_bar_cnt, 1u) == NB - 1) {
            *(volatile unsigned*)&g_bar_cnt = 0u;
            __threadfence();
            *(volatile unsigned*)&g_bar_gen = gen + 1u;
        } else {
            while (*(volatile unsigned*)&g_bar_gen == gen) { __nanosleep(32); }
        }
    }
    __syncthreads();
}
__device__ __forceinline__ void grid_sync_init() {
    __syncthreads();
    if (threadIdx.x == 0) {
        __threadfence();
        unsigned gen = *(volatile unsigned*)&g_bar_gen;
        if (atomicAdd(&g_bar_cnt, 1u) == NB - 1) {
            *(volatile unsigned*)&g_bar_cnt = 0u;
            __threadfence();
            *(volatile unsigned*)&g_bar_gen = gen + 1u;
        } else {
            while (*(volatile unsigned*)&g_bar_gen == gen) { __nanosleep(32); }
        }
        __threadfence();   // acquire (once)
    }
    __syncthreads();
}

__global__ void __launch_bounds__(NT, 2) mega(
    const float* __restrict__ noise, const float* __restrict__ edge_attr,
    const int* __restrict__ eidx,
    const float* __restrict__ fc1_w, const float* __restrict__ fc1_b,
    const float* __restrict__ qw, const float* __restrict__ qb,
    const float* __restrict__ kw, const float* __restrict__ kb,
    const float* __restrict__ vw, const float* __restrict__ vb,
    const float* __restrict__ ew,
    const float* __restrict__ sw, const float* __restrict__ sb,
    const float* __restrict__ atom_w, const float* __restrict__ atom_b,
    const float* __restrict__ other_w, const float* __restrict__ other_b,
    const float* __restrict__ efw, const float* __restrict__ efb,
    float* __restrict__ out)
{
    extern __shared__ __align__(16) float smem[];
    const int t = threadIdx.x, blk = blockIdx.x;
    const int w = t >> 5, lane = t & 31;

    // ================= init =================
    if (blk < BB && t < HH) {
        float acc = fc1_b[t];
        #pragma unroll 4
        for (int i = 0; i < 128; i++) acc += noise[blk*128 + i] * fc1_w[i*HH + t];
        acc = fmaxf(acc, 0.f);
        for (int n = 0; n < NN; n++) g_bufA[(blk*NN + n)*HH + t] = acc;
    }
    { int e = blk*NT + t; if (e < NEdg) g_eid[eidx[e]*NN + eidx[NEdg + e]] = e; }
    grid_sync_init();

    float* xin = g_bufA;
    float* xout = g_bufB;

    for (int l = 0; l < LL; l++) {
        // ============ proj: mma.sync bf16 hi/lo 3-pass, 64x64xK128 tiles (208 jobs) ============
        if (blk < 208) {
            uint2* Ap = (uint2*)smem;          // [64][68]: (hi,lo) pairs along k
            uint2* Bp = ((uint2*)smem) + A_U2; // [64 kp][68]: (hi,lo), k-pair rows
            int ct = blk % 26, rt = blk / 26;
            const float* W; const float* bias; int ld, coff; float* outp;
            if (ct < 8)       { W = qw + l*HH*INNER; bias = qb + l*INNER; ld = INNER; coff = ct*64;      outp = g_q; }
            else if (ct < 16) { W = kw + l*HH*INNER; bias = kb + l*INNER; ld = INNER; coff = (ct-8)*64;  outp = g_k; }
            else if (ct < 24) { W = vw + l*HH*INNER; bias = vb + l*INNER; ld = INNER; coff = (ct-16)*64; outp = g_v; }
            else              { W = sw + l*HH*HH;    bias = sb + l*HH;    ld = HH;    coff = (ct-24)*64; outp = xout; }
            int r0 = rt * 64;

            // ---- stage A: relu(xin) -> (hi,lo) pairs; kp strided by 4 (phase-conflict-free STS) ----
            {
                int row = t >> 2, q = t & 3;
                const float* xr = &xin[(r0 + row)*HH];
                #pragma unroll
                for (int i = 0; i < 16; i++) {
                    int kp = q + 4*i;
                    float2 v = __ldcg((const float2*)&xr[2*kp]);
                    Ap[row*APITCH + kp] = bfsplit(fmaxf(v.x, 0.f), fmaxf(v.y, 0.f));
                }
            }
            // ---- stage B: W -> (hi,lo) k-pair-packed [kp][n] ----
            {
                int n = t & 63, cg = t >> 6;
                const float* wp = &W[coff + n];
                #pragma unroll
                for (int i = 0; i < 16; i++) {
                    int kp = cg + 4*i;
                    float f0 = wp[(size_t)(2*kp)*ld];
                    float f1 = wp[(size_t)(2*kp + 1)*ld];
                    Bp[kp*APITCH + n] = bfsplit(f0, f1);
                }
            }
            __syncthreads();

            // ---- mainloop: warp w -> m-tile mt=w&3 (16 rows), n-half nh=w>>2 (4 n8-tiles) ----
            {
                int mt = w & 3, nh = w >> 2;
                int g = lane >> 2, tid = lane & 3;
                float acc[4][4] = {};
                const uint2* Abase = Ap + (mt*16)*APITCH;
                #pragma unroll
                for (int s = 0; s < 8; s++) {
                    int kp0 = 8*s + tid;
                    uint2 a0 = Abase[g*APITCH + kp0];
                    uint2 a1 = Abase[(g+8)*APITCH + kp0];
                    uint2 a2 = Abase[g*APITCH + kp0 + 4];
                    uint2 a3 = Abase[(g+8)*APITCH + kp0 + 4];
                    #pragma unroll
                    for (int nt = 0; nt < 4; nt++) {
                        int n = nh*32 + nt*8 + g;
                        uint2 b0 = Bp[kp0*APITCH + n];
                        uint2 b1 = Bp[(kp0+4)*APITCH + n];
                        mma_bf16(acc[nt], a0.x, a1.x, a2.x, a3.x, b0.x, b1.x);  // hi*hi
                        mma_bf16(acc[nt], a0.x, a1.x, a2.x, a3.x, b0.y, b1.y);  // hi*lo
                        mma_bf16(acc[nt], a0.y, a1.y, a2.y, a3.y, b0.x, b1.x);  // lo*hi
                    }
                }
                // ---- writeback + bias ----
                int row0 = r0 + mt*16 + g;
                #pragma unroll
                for (int nt = 0; nt < 4; nt++) {
                    int col = coff + nh*32 + nt*8 + 2*tid;
                    float2 bv = *(const float2*)&bias[col];
                    float2 o0 = {acc[nt][0] + bv.x, acc[nt][1] + bv.y};
                    float2 o1 = {acc[nt][2] + bv.x, acc[nt][3] + bv.y};
                    *(float2*)&outp[(size_t)row0*ld + col] = o0;
                    *(float2*)&outp[(size_t)(row0+8)*ld + col] = o1;
                }
            }
        }
        grid_sync_fast();

        // ============ attn: identical to R12 ============
        {
            float* sKV = smem;            // [64][128]: K swizzled, then V linear
            float* sQ  = smem + 8192;
            float* sEw = smem + 9216;
            float (*sS)[68] = (float(*)[68])(smem + 10240);
            float* sQE = smem + 10784;
            float* sAE = smem + 10848;
            int jseg = blk & 7;
            int h = (blk >> 3) & 3;
            int b = blk >> 5;
            int jbase = jseg * JB;
            const float scale = 0.08838834764831845f;  // 1/sqrt(128)

            {   int idx = t * 4;
                *(float4*)&sEw[idx] = *(const float4*)&ew[((size_t)l*EE + (idx >> 7))*INNER + h*HD + (idx & 127)];
            }
            {   int idx = t * 4;
                *(float4*)&sQ[idx] = __ldcg((const float4*)&g_q[(b*NN + jbase + (idx >> 7))*INNER + h*HD + (idx & 127)]);
            }
            for (int q4 = t; q4 < NN*32; q4 += NT) {
                int row = q4 >> 5, dq = (q4 & 31) << 2;
                float4 v = __ldcg((const float4*)&g_k[(b*NN + row)*INNER + h*HD + dq]);
                int rx = row & 31;
                float* base = &sKV[row*128];
                float2 lo = {v.x, v.y}, hi = {v.z, v.w};
                *(float2*)&base[((dq >> 1) ^ rx) << 1] = lo;
                *(float2*)&base[(((dq >> 1) + 1) ^ rx) << 1] = hi;
            }
            __syncthreads();

            {
                const float* qrow = &sQ[w*HD];
                int f = lane & 7, seg = lane >> 3;
                const float* ewrow = &sEw[f*HD + seg*32];
                const float* qseg  = qrow + seg*32;
                float p = 0.f;
                #pragma unroll
                for (int i = 0; i < 32; i++) {
                    int d = (i + lane) & 31;
                    p += qseg[d] * ewrow[d];
                }
                p += __shfl_xor_sync(0xffffffffu, p, 8);
                p += __shfl_xor_sync(0xffffffffu, p, 16);
                if (lane < 8) sQE[w*8 + lane] = p;
            }
            __syncthreads();

            {
                int jp = w >> 1, ih = w & 1;
                int i = ih*32 + lane;
                int jl0 = jp*2, jl1 = jp*2 + 1;
                int j0 = jbase + jl0, j1 = jbase + jl1;
                const ull* q0p = (const ull*)&sQ[jl0*HD];
                const ull* q1p = (const ull*)&sQ[jl1*HD];
                const float* kr = &sKV[i*128];
                ull A0 = 0ull, A1 = 0ull;
                #pragma unroll 8
                for (int d2 = 0; d2 < 64; d2++) {
                    ull kv = *(const ull*)&kr[(d2 ^ lane) << 1];
                    A0 = fma2(q0p[d2], kv, A0);
                    A1 = fma2(q1p[d2], kv, A1);
                }
                float dot0 = f2sum(A0), dot1 = f2sum(A1);
                const float* eabase = edge_attr + (size_t)b * NEdg * EE;
                int e0 = (i == j0) ? 0 : g_eid[i*NN + j0];
                int e1 = (i == j1) ? 0 : g_eid[i*NN + j1];
                float4 p0a = *(const float4*)&eabase[e0*EE];
                float4 p0b = *(const float4*)&eabase[e0*EE + 4];
                float4 p1a = *(const float4*)&eabase[e1*EE];
                float4 p1b = *(const float4*)&eabase[e1*EE + 4];
                const float* qe0 = &sQE[jl0*8];
                const float* qe1 = &sQE[jl1*8];
                float bs0 = p0a.x*qe0[0] + p0a.y*qe0[1] + p0a.z*qe0[2] + p0a.w*qe0[3]
                          + p0b.x*qe0[4] + p0b.y*qe0[5] + p0b.z*qe0[6] + p0b.w*qe0[7];
                float bs1 = p1a.x*qe1[0] + p1a.y*qe1[1] + p1a.z*qe1[2] + p1a.w*qe1[3]
                          + p1b.x*qe1[4] + p1b.y*qe1[5] + p1b.z*qe1[6] + p1b.w*qe1[7];
                sS[jl0][i] = (i == j0) ? -1e30f : (dot0 + bs0) * scale;
                sS[jl1][i] = (i == j1) ? -1e30f : (dot1 + bs1) * scale;
            }
            __syncthreads();

            for (int idx = t*4; idx < NN*HD; idx += NT*4)
                *(float4*)&sKV[idx] = __ldcg((const float4*)&g_v[(b*NN + (idx >> 7))*INNER + h*HD + (idx & 127)]);

            {
                int jg = jbase + w;
                float s1 = sS[w][lane], s2 = sS[w][lane + 32];
                float m = fmaxf(s1, s2);
                #pragma unroll
                for (int o = 1; o < 32; o <<= 1) m = fmaxf(m, __shfl_xor_sync(0xffffffffu, m, o));
                float x1 = __expf(s1 - m), x2 = __expf(s2 - m);
                float sum = x1 + x2;
                #pragma unroll
                for (int o = 1; o < 32; o <<= 1) sum += __shfl_xor_sync(0xffffffffu, sum, o);
                float inv = 1.f / sum;
                float al1 = x1 * inv, al2 = x2 * inv;
                sS[w][lane] = al1;
                sS[w][lane + 32] = al2;
                int i1 = lane, i2 = lane + 32;
                const float* eabase = edge_attr + (size_t)b * NEdg * EE;
                int e1 = (i1 == jg) ? 0 : g_eid[i1*NN + jg];
                int e2 = (i2 == jg) ? 0 : g_eid[i2*NN + jg];
                float4 ea1a = *(const float4*)&eabase[e1*EE];
                float4 ea1b = *(const float4*)&eabase[e1*EE + 4];
                float4 ea2a = *(const float4*)&eabase[e2*EE];
                float4 ea2b = *(const float4*)&eabase[e2*EE + 4];
                float ea1[8] = {ea1a.x, ea1a.y, ea1a.z, ea1a.w, ea1b.x, ea1b.y, ea1b.z, ea1b.w};
                float ea2[8] = {ea2a.x, ea2a.y, ea2a.z, ea2a.w, ea2b.x, ea2b.y, ea2b.z, ea2b.w};
                float ae[8];
                #pragma unroll
                for (int f = 0; f < 8; f++) {
                    float v = al1*ea1[f] + al2*ea2[f];
                    #pragma unroll
                    for (int o = 1; o < 32; o <<= 1) v += __shfl_xor_sync(0xffffffffu, v, o);
                    ae[f] = v;
                }
                if (lane == 0) {
                    #pragma unroll
                    for (int f = 0; f < 8; f++) sAE[w*8 + f] = ae[f];
                }
            }
            __syncthreads();

            {
                int jp2 = w >> 1, dh = w & 1;
                int jl0 = jp2*2, jl1 = jl0 + 1;
                int d0 = dh*64 + lane*2;
                float a00 = 0.f, a01 = 0.f, a10 = 0.f, a11 = 0.f;
                #pragma unroll 4
                for (int i = 0; i < NN; i++) {
                    float al0 = sS[jl0][i], al1 = sS[jl1][i];
                    float2 v = *(const float2*)&sKV[i*HD + d0];
                    a00 += al0*v.x; a01 += al0*v.y;
                    a10 += al1*v.x; a11 += al1*v.y;
                }
                #pragma unroll
                for (int f = 0; f < 8; f++) {
                    float ae0 = sAE[jl0*8 + f], ae1 = sAE[jl1*8 + f];
                    float2 wv = *(const float2*)&sEw[f*HD + d0];
                    a00 += ae0*wv.x; a01 += ae0*wv.y;
                    a10 += ae1*wv.x; a11 += ae1*wv.y;
                }
                float* d0p = &xout[(b*NN + jbase + jl0)*HH + d0];
                float* d1p = &xout[(b*NN + jbase + jl1)*HH + d0];
                atomicAdd(d0p+0, 0.25f*a00);
                atomicAdd(d0p+1, 0.25f*a01);
                atomicAdd(d1p+0, 0.25f*a10);
                atomicAdd(d1p+1, 0.25f*a11);
            }
        }
        grid_sync_fast();
        float* tmp = xin; xin = xout; xout = tmp;
    }

    // ================= node head + P/D (2 nodes per block) =================
    {
        float* xr   = smem;
        float* outs = smem + 256;
        float* red  = smem + 336;
        int sub = t >> 7, tl = t & 127;
        int node = blk*2 + sub;
        xr[sub*128 + tl] = fmaxf(__ldcg(&xin[node*128 + tl]), 0.f);
        __syncthreads();
        if (tl < 40) {
            const float* xp = &xr[sub*128];
            float acc;
            if (tl < 9)       { acc = atom_b[tl];  for (int d = 0; d < HH; d++) acc += xp[d]*atom_w[d*9+tl]; }
            else if (tl < 24) { int c = tl-9;  acc = other_b[c]; for (int d = 0; d < HH; d++) acc += xp[d]*other_w[d*15+c]; }
            else if (tl < 32) { int f = tl-24; acc = 0.f; for (int d = 0; d < HH; d++) acc += xp[d]*efw[d*EE+f]; }
            else              { int f = tl-32; acc = 0.f; for (int d = 0; d < HH; d++) acc += xp[d]*efw[(128+d)*EE+f]; }
            outs[sub*40 + tl] = acc;
        }
        __syncthreads();
        if (tl == 0) {
            float m = -1e30f;
            for (int a = 0; a < 9; a++) m = fmaxf(m, outs[sub*40+a]);
            float s = 0.f;
            for (int a = 0; a < 9; a++) s += __expf(outs[sub*40+a]-m);
            red[sub*2] = m; red[sub*2+1] = s;
        }
        __syncthreads();
        if (tl < 9) {
            float p = __expf(outs[sub*40+tl]-red[sub*2]) / red[sub*2+1];
            out[node*24 + tl] = 1.f/(1.f + __expf(-p));
        } else if (tl < 24) {
            float o = 1.f/(1.f + __expf(-outs[sub*40+tl]));
            out[node*24 + tl] = 1.f/(1.f + __expf(-o));
        } else if (tl < 32) {
            g_P[node*EE + (tl-24)] = outs[sub*40+tl];
        } else if (tl < 40) {
            g_D[node*EE + (tl-32)] = outs[sub*40+tl];
        }
    }
    grid_sync_fast();

    // ================= edge head =================
    if (t < 126) {
        int eg = blk*126 + t;     // 256*126 = 32256
        int b = eg / NEdg, e = eg % NEdg;
        int s = eidx[e], d = eidx[NEdg + e];
        float4 Pa = __ldcg((const float4*)&g_P[(b*NN + s)*EE]);
        float4 Pb = __ldcg((const float4*)&g_P[(b*NN + s)*EE + 4]);
        float4 Da = __ldcg((const float4*)&g_D[(b*NN + d)*EE]);
        float4 Db = __ldcg((const float4*)&g_D[(b*NN + d)*EE + 4]);
        float P[8] = {Pa.x, Pa.y, Pa.z, Pa.w, Pb.x, Pb.y, Pb.z, Pb.w};
        float D[8] = {Da.x, Da.y, Da.z, Da.w, Db.x, Db.y, Db.z, Db.w};
        float* o = out + (size_t)ROWS*24 + (size_t)eg*EE;
        #pragma unroll
        for (int f = 0; f < EE; f++) {
            float v = P[f] + D[f] + efb[f];
            o[f] = 1.f/(1.f + __expf(-v));
        }
    }
}

extern "C" void kernel_launch(void* const* d_in, const int* in_sizes, int n_in,
                              void* d_out, int out_size) {
    const float* noise     = (const float*)d_in[0];
    const float* edge_attr = (const float*)d_in[1];
    const int*   edge_index= (const int*)  d_in[2];
    const float* fc1_w     = (const float*)d_in[3];
    const float* fc1_b     = (const float*)d_in[4];
    const float* q_w       = (const float*)d_in[5];
    const float* q_b       = (const float*)d_in[6];
    const float* k_w       = (const float*)d_in[7];
    const float* k_b       = (const float*)d_in[8];
    const float* v_w       = (const float*)d_in[9];
    const float* v_b       = (const float*)d_in[10];
    const float* e_w       = (const float*)d_in[11];
    const float* skip_w    = (const float*)d_in[12];
    const float* skip_b    = (const float*)d_in[13];
    const float* atom_w    = (const float*)d_in[14];
    const float* atom_b    = (const float*)d_in[15];
    const float* other_w   = (const float*)d_in[16];
    const float* other_b   = (const float*)d_in[17];
    const float* efw       = (const float*)d_in[18];
    const float* efb       = (const float*)d_in[19];
    float* out = (float*)d_out;

    cudaFuncSetAttribute(mega, cudaFuncAttributeMaxDynamicSharedMemorySize, SMEM_BYTES);
    cudaFuncSetAttribute(mega, cudaFuncAttributePreferredSharedMemoryCarveout, 100);
    mega<<<NB, NT, SMEM_BYTES>>>(noise, edge_attr, edge_index, fc1_w, fc1_b,
                     q_w, q_b, k_w, k_b, v_w, v_b, e_w, skip_w, skip_b,
                     atom_w, atom_b, other_w, other_b, efw, efb, out);
}